// round 1
// baseline (speedup 1.0000x reference)
#include <cuda_runtime.h>
#include <math.h>
#include <stdint.h>

// Problem dims (fixed by setup_inputs)
#define CDIM 8192
#define DDIM 512

// GEMM tiling
#define BM 64
#define BN 128
#define BK 16
#define NJT (CDIM / BN)       // 64 column tiles
#define BSTRIDE (BN + 4)      // padded k-major B tile stride (2-way max conflicts on fill)

// Device scratch (static allocation is allowed; cudaMalloc is not)
__device__ float g_Gn[CDIM * DDIM];   // normalized embeddings, 16 MB
__device__ float g_margin[CDIM];
__device__ int   g_ms[CDIM];
__device__ int   g_ls[CDIM];
__device__ float g_terms[CDIM];

// ---------------------------------------------------------------------------
// Kernel 1: row-wise L2 normalize. One block per row, 128 threads, float4.
// ---------------------------------------------------------------------------
__global__ void __launch_bounds__(128) normalize_kernel(const float* __restrict__ G) {
    const int row = blockIdx.x;
    const int t = threadIdx.x;
    const float4* src = (const float4*)(G + (size_t)row * DDIM);
    float4 v = src[t];  // 128 threads * 4 = 512
    float ss = v.x * v.x + v.y * v.y + v.z * v.z + v.w * v.w;
    #pragma unroll
    for (int o = 16; o; o >>= 1) ss += __shfl_xor_sync(0xffffffffu, ss, o);
    __shared__ float ws[4];
    if ((t & 31) == 0) ws[t >> 5] = ss;
    __syncthreads();
    float tot = ws[0] + ws[1] + ws[2] + ws[3];
    float inv = rsqrtf(tot);
    float4 o4 = make_float4(v.x * inv, v.y * inv, v.z * inv, v.w * inv);
    ((float4*)(g_Gn + (size_t)row * DDIM))[t] = o4;
}

// ---------------------------------------------------------------------------
// Kernel 2: fused S = Gn @ Gn^T with per-row {argmax, argmin, sum exp} epilogue.
// Block = 64 rows (BM). A tile (64x512) resident in smem k-major.
// 256 threads = 16x16; thread (ty,tx) computes rows ty*4..+3, cols tx*8..+7.
// Row state replicated across the 16 tx lanes; butterfly shuffles reduce.
// ---------------------------------------------------------------------------
extern __shared__ float smem_dyn[];

__global__ void __launch_bounds__(256) fused_sim_kernel() {
    float* As = smem_dyn;                    // [DDIM][BM] k-major
    float* Bs = smem_dyn + DDIM * BM;        // [BK][BSTRIDE] k-major

    const int tid = threadIdx.x;
    const int tx = tid & 15;
    const int ty = tid >> 4;
    const int row0 = blockIdx.x * BM;

    // ---- Fill A tile once: rows row0..row0+63, transposed to k-major ----
    #pragma unroll
    for (int it = 0; it < (BM * DDIM / 4) / 256; ++it) {  // 32 iters
        int idx = it * 256 + tid;
        int r = idx >> 7;        // 0..63
        int c4 = idx & 127;      // 0..127 float4s along D
        float4 v = ((const float4*)(g_Gn + (size_t)(row0 + r) * DDIM))[c4];
        int k = c4 * 4;
        As[(k + 0) * BM + r] = v.x;
        As[(k + 1) * BM + r] = v.y;
        As[(k + 2) * BM + r] = v.z;
        As[(k + 3) * BM + r] = v.w;
    }

    // ---- Per-row online state (replicated across 16 tx lanes) ----
    float st_mx[4], st_mn[4], st_z[4];
    int st_ix[4], st_in[4];
    int gr[4];
    #pragma unroll
    for (int r = 0; r < 4; ++r) {
        st_mx[r] = -2.0f; st_mn[r] = 2.0f; st_z[r] = 0.0f;
        st_ix[r] = 0x7fffffff; st_in[r] = 0x7fffffff;
        gr[r] = row0 + ty * 4 + r;
    }

    for (int jt = 0; jt < NJT; ++jt) {
        const int j0 = jt * BN;
        float acc[4][8];
        #pragma unroll
        for (int r = 0; r < 4; ++r)
            #pragma unroll
            for (int c = 0; c < 8; ++c) acc[r][c] = 0.0f;

        for (int kt = 0; kt < DDIM; kt += BK) {
            __syncthreads();  // Bs free (and As visible on first pass)
            // Fill B tile: rows j0..j0+127, cols kt..kt+15, transposed to k-major
            #pragma unroll
            for (int it = 0; it < 2; ++it) {
                int idx = it * 256 + tid;
                int r = idx >> 2;        // 0..127
                int c4 = idx & 3;        // 0..3
                float4 v = ((const float4*)(g_Gn + (size_t)(j0 + r) * DDIM + kt))[c4];
                int k = c4 * 4;
                Bs[(k + 0) * BSTRIDE + r] = v.x;
                Bs[(k + 1) * BSTRIDE + r] = v.y;
                Bs[(k + 2) * BSTRIDE + r] = v.z;
                Bs[(k + 3) * BSTRIDE + r] = v.w;
            }
            __syncthreads();

            #pragma unroll
            for (int k = 0; k < BK; ++k) {
                float4 a  = *(const float4*)(As + (kt + k) * BM + ty * 4);
                float4 b0 = *(const float4*)(Bs + k * BSTRIDE + tx * 8);
                float4 b1 = *(const float4*)(Bs + k * BSTRIDE + tx * 8 + 4);
                float av[4] = {a.x, a.y, a.z, a.w};
                float bv[8] = {b0.x, b0.y, b0.z, b0.w, b1.x, b1.y, b1.z, b1.w};
                #pragma unroll
                for (int r = 0; r < 4; ++r)
                    #pragma unroll
                    for (int c = 0; c < 8; ++c)
                        acc[r][c] = fmaf(av[r], bv[c], acc[r][c]);
            }
        }

        // ---- Epilogue for this 64x128 tile ----
        #pragma unroll
        for (int r = 0; r < 4; ++r) {
            const int gi = gr[r];
            float vmx = -2.0f, vmn = 2.0f, s = 0.0f;
            int imx = 0x7fffffff, imn = 0x7fffffff;
            #pragma unroll
            for (int c = 0; c < 8; ++c) {
                int gj = j0 + tx * 8 + c;
                float v = acc[r][c];
                if (gj != gi) {            // exclude diagonal
                    s += __expf(v);
                    if (v > vmx) { vmx = v; imx = gj; }   // first-index tie-break (ascending scan)
                    if (v < vmn) { vmn = v; imn = gj; }
                }
            }
            // butterfly across the 16 lanes sharing this row
            #pragma unroll
            for (int o = 8; o; o >>= 1) {
                float ov = __shfl_xor_sync(0xffffffffu, vmx, o);
                int   oi = __shfl_xor_sync(0xffffffffu, imx, o);
                if (ov > vmx || (ov == vmx && oi < imx)) { vmx = ov; imx = oi; }
                ov = __shfl_xor_sync(0xffffffffu, vmn, o);
                oi = __shfl_xor_sync(0xffffffffu, imn, o);
                if (ov < vmn || (ov == vmn && oi < imn)) { vmn = ov; imn = oi; }
                s += __shfl_xor_sync(0xffffffffu, s, o);
            }
            if (vmx > st_mx[r] || (vmx == st_mx[r] && imx < st_ix[r])) { st_mx[r] = vmx; st_ix[r] = imx; }
            if (vmn < st_mn[r] || (vmn == st_mn[r] && imn < st_in[r])) { st_mn[r] = vmn; st_in[r] = imn; }
            st_z[r] += s;
        }
    }

    if (tx == 0) {
        #pragma unroll
        for (int r = 0; r < 4; ++r) {
            int gi = gr[r];
            g_ms[gi] = st_ix[r];
            g_ls[gi] = st_in[r];
            // margin = P[ms] - P[ls] = (exp(mx) - exp(mn)) / sum_offdiag exp(S)
            g_margin[gi] = (__expf(st_mx[r]) - __expf(st_mn[r])) / st_z[r];
        }
    }
}

// ---------------------------------------------------------------------------
// Kernel 3: per-row triplet term. One block per row, 128 threads.
// ---------------------------------------------------------------------------
__global__ void __launch_bounds__(128) dist_kernel(const float* __restrict__ w) {
    const int i = blockIdx.x;
    const int t = threadIdx.x;
    const int ms = g_ms[i];
    const int ls = g_ls[i];
    float4 a = ((const float4*)(w + (size_t)i  * DDIM))[t];
    float4 b = ((const float4*)(w + (size_t)ms * DDIM))[t];
    float4 c = ((const float4*)(w + (size_t)ls * DDIM))[t];
    float dx, dm, dl;
    dx = a.x - b.x; dm  = dx * dx;
    dx = a.y - b.y; dm += dx * dx;
    dx = a.z - b.z; dm += dx * dx;
    dx = a.w - b.w; dm += dx * dx;
    dx = a.x - c.x; dl  = dx * dx;
    dx = a.y - c.y; dl += dx * dx;
    dx = a.z - c.z; dl += dx * dx;
    dx = a.w - c.w; dl += dx * dx;
    #pragma unroll
    for (int o = 16; o; o >>= 1) {
        dm += __shfl_xor_sync(0xffffffffu, dm, o);
        dl += __shfl_xor_sync(0xffffffffu, dl, o);
    }
    __shared__ float sm[4], sl[4];
    if ((t & 31) == 0) { sm[t >> 5] = dm; sl[t >> 5] = dl; }
    __syncthreads();
    if (t == 0) {
        float tm = sm[0] + sm[1] + sm[2] + sm[3];
        float tl = sl[0] + sl[1] + sl[2] + sl[3];
        g_terms[i] = fmaxf(0.0f, sqrtf(tm) - sqrtf(tl) + g_margin[i]);
    }
}

// ---------------------------------------------------------------------------
// Kernel 4: deterministic mean reduction, single block.
// ---------------------------------------------------------------------------
__global__ void __launch_bounds__(256) reduce_kernel(float* __restrict__ out) {
    __shared__ float sm[256];
    const int t = threadIdx.x;
    float s = 0.0f;
    for (int i = t; i < CDIM; i += 256) s += g_terms[i];
    sm[t] = s;
    __syncthreads();
    for (int o = 128; o; o >>= 1) {
        if (t < o) sm[t] += sm[t + o];
        __syncthreads();
    }
    if (t == 0) out[0] = sm[0] * (1.0f / (float)CDIM);
}

// ---------------------------------------------------------------------------
extern "C" void kernel_launch(void* const* d_in, const int* in_sizes, int n_in,
                              void* d_out, int out_size) {
    const float* G = (const float*)d_in[0];  // gt_class_embeddings [8192, 512]
    const float* w = (const float*)d_in[1];  // w [8192, 512]
    float* out = (float*)d_out;

    const int smem_bytes = DDIM * BM * 4 + BK * BSTRIDE * 4;  // 139520
    cudaFuncSetAttribute(fused_sim_kernel,
                         cudaFuncAttributeMaxDynamicSharedMemorySize, smem_bytes);

    normalize_kernel<<<CDIM, 128>>>(G);
    fused_sim_kernel<<<CDIM / BM, 256, smem_bytes>>>();
    dist_kernel<<<CDIM, 128>>>(w);
    reduce_kernel<<<1, 256>>>(out);
}

// round 2
// speedup vs baseline: 1.8817x; 1.8817x over previous
#include <cuda_runtime.h>
#include <math.h>
#include <stdint.h>

#define CDIM 8192
#define DDIM 512

#define BM 128              // rows per block
#define BN 128              // cols per tile
#define BK 16               // k-chunk
#define NSL 4               // column slices
#define SLW (CDIM / NSL)    // 2048 cols per slice
#define NJT (SLW / BN)      // 16 col tiles per block
#define NRB (CDIM / BM)     // 64 row blocks
#define NCH (DDIM / BK)     // 32 k-chunks
#define AST 132             // padded smem k-row stride (floats)

typedef unsigned long long u64;

// static device scratch (no cudaMalloc allowed)
__device__ float g_Gn[CDIM * DDIM];        // 16 MB normalized embeddings
__device__ float g_pmx[NSL * CDIM];
__device__ float g_pmn[NSL * CDIM];
__device__ float g_pz [NSL * CDIM];
__device__ int   g_pix[NSL * CDIM];
__device__ int   g_pin[NSL * CDIM];
__device__ float g_margin[CDIM];
__device__ int   g_ms[CDIM];
__device__ int   g_ls[CDIM];
__device__ float g_terms[CDIM];

// ---- packed fp32x2 helpers (Blackwell FFMA2 path) ----
__device__ __forceinline__ u64 pack2(float lo, float hi) {
    u64 r; asm("mov.b64 %0, {%1, %2};" : "=l"(r) : "f"(lo), "f"(hi)); return r;
}
__device__ __forceinline__ void unpack2(u64 v, float& lo, float& hi) {
    asm("mov.b64 {%0, %1}, %2;" : "=f"(lo), "=f"(hi) : "l"(v));
}
__device__ __forceinline__ void ffma2(u64& d, u64 a, u64 b) {
    asm("fma.rn.f32x2 %0, %1, %2, %0;" : "+l"(d) : "l"(a), "l"(b));
}

// ---------------------------------------------------------------------------
// Kernel 1: row-wise L2 normalize.
// ---------------------------------------------------------------------------
__global__ void __launch_bounds__(128) normalize_kernel(const float* __restrict__ G) {
    const int row = blockIdx.x;
    const int t = threadIdx.x;
    float4 v = ((const float4*)(G + (size_t)row * DDIM))[t];
    float ss = v.x * v.x + v.y * v.y + v.z * v.z + v.w * v.w;
    #pragma unroll
    for (int o = 16; o; o >>= 1) ss += __shfl_xor_sync(0xffffffffu, ss, o);
    __shared__ float ws[4];
    if ((t & 31) == 0) ws[t >> 5] = ss;
    __syncthreads();
    float inv = rsqrtf(ws[0] + ws[1] + ws[2] + ws[3]);
    ((float4*)(g_Gn + (size_t)row * DDIM))[t] =
        make_float4(v.x * inv, v.y * inv, v.z * inv, v.w * inv);
}

// ---------------------------------------------------------------------------
// Kernel 2: fused S = Gn @ Gn^T with per-row {argmax, argmin, sum exp}.
// Grid: 64 row-blocks x 4 column slices. Block: 256 threads, 8x8 micro-tile,
// packed f32x2 FMAs, double-buffered smem staging.
// ---------------------------------------------------------------------------
__global__ void __launch_bounds__(256) fused_sim_kernel() {
    __shared__ float As[2][BK * AST];
    __shared__ float Bs[2][BK * AST];

    const int tid = threadIdx.x;
    const int tx = tid & 15;
    const int ty = tid >> 4;
    const int rb = blockIdx.x & (NRB - 1);
    const int sl = blockIdx.x >> 6;
    const int row0 = rb * BM;
    const int col0 = sl * SLW;

    // fill-thread mapping: row fr (+64 on 2nd half), k-group fc4
    const int fr  = tid >> 2;   // 0..63
    const int fc4 = tid & 3;    // 0..3 -> k = fc4*4..+3

    // per-lane running state for the 8 rows this thread owns
    float mx[8], mn[8], zz[8];
    int ix[8], iN[8];
    #pragma unroll
    for (int r = 0; r < 8; ++r) {
        mx[r] = -2.0f; mn[r] = 2.0f; zz[r] = 0.0f;
        ix[r] = 0x7fffffff; iN[r] = 0x7fffffff;
    }

    for (int jt = 0; jt < NJT; ++jt) {
        const int j0 = col0 + jt * BN;

        u64 acc[8][4];
        #pragma unroll
        for (int r = 0; r < 8; ++r)
            #pragma unroll
            for (int c = 0; c < 4; ++c) acc[r][c] = 0ull;

        // ---- prologue: fill buffer 0 with chunk 0 ----
        {
            #pragma unroll
            for (int h = 0; h < 2; ++h) {
                const int r = fr + h * 64;
                float4 va = *(const float4*)(g_Gn + (size_t)(row0 + r) * DDIM + fc4 * 4);
                float4 vb = *(const float4*)(g_Gn + (size_t)(j0  + r) * DDIM + fc4 * 4);
                const int k0 = fc4 * 4;
                As[0][(k0 + 0) * AST + r] = va.x;
                As[0][(k0 + 1) * AST + r] = va.y;
                As[0][(k0 + 2) * AST + r] = va.z;
                As[0][(k0 + 3) * AST + r] = va.w;
                Bs[0][(k0 + 0) * AST + r] = vb.x;
                Bs[0][(k0 + 1) * AST + r] = vb.y;
                Bs[0][(k0 + 2) * AST + r] = vb.z;
                Bs[0][(k0 + 3) * AST + r] = vb.w;
            }
        }
        __syncthreads();

        for (int ch = 0; ch < NCH; ++ch) {
            const int buf = ch & 1;
            const bool more = (ch + 1 < NCH);
            float4 pa[2], pb[2];
            if (more) {
                const int kt = (ch + 1) * BK;
                #pragma unroll
                for (int h = 0; h < 2; ++h) {
                    const int r = fr + h * 64;
                    pa[h] = *(const float4*)(g_Gn + (size_t)(row0 + r) * DDIM + kt + fc4 * 4);
                    pb[h] = *(const float4*)(g_Gn + (size_t)(j0  + r) * DDIM + kt + fc4 * 4);
                }
            }

            #pragma unroll
            for (int k = 0; k < BK; ++k) {
                const float* ak = &As[buf][k * AST];
                const float* bk = &Bs[buf][k * AST];
                float4 a0 = *(const float4*)(ak + ty * 4);
                float4 a1 = *(const float4*)(ak + 64 + ty * 4);
                float4 b0 = *(const float4*)(bk + tx * 4);
                float4 b1 = *(const float4*)(bk + 64 + tx * 4);
                u64 bp[4] = { pack2(b0.x, b0.y), pack2(b0.z, b0.w),
                              pack2(b1.x, b1.y), pack2(b1.z, b1.w) };
                float av[8] = {a0.x, a0.y, a0.z, a0.w, a1.x, a1.y, a1.z, a1.w};
                #pragma unroll
                for (int r = 0; r < 8; ++r) {
                    u64 ap = pack2(av[r], av[r]);
                    #pragma unroll
                    for (int c = 0; c < 4; ++c) ffma2(acc[r][c], ap, bp[c]);
                }
            }

            if (more) {
                const int nb = buf ^ 1;
                #pragma unroll
                for (int h = 0; h < 2; ++h) {
                    const int r = fr + h * 64;
                    const int k0 = fc4 * 4;
                    As[nb][(k0 + 0) * AST + r] = pa[h].x;
                    As[nb][(k0 + 1) * AST + r] = pa[h].y;
                    As[nb][(k0 + 2) * AST + r] = pa[h].z;
                    As[nb][(k0 + 3) * AST + r] = pa[h].w;
                    Bs[nb][(k0 + 0) * AST + r] = pb[h].x;
                    Bs[nb][(k0 + 1) * AST + r] = pb[h].y;
                    Bs[nb][(k0 + 2) * AST + r] = pb[h].z;
                    Bs[nb][(k0 + 3) * AST + r] = pb[h].w;
                }
                __syncthreads();
            }
        }

        // ---- per-lane epilogue for this 128x128 tile (no shuffles) ----
        #pragma unroll
        for (int r = 0; r < 8; ++r) {
            const int gi = row0 + ((r < 4) ? (ty * 4 + r) : (64 + ty * 4 + (r - 4)));
            #pragma unroll
            for (int c = 0; c < 4; ++c) {
                float v0, v1;
                unpack2(acc[r][c], v0, v1);
                const int j = j0 + ((c < 2) ? (tx * 4 + c * 2)
                                            : (64 + tx * 4 + (c - 2) * 2));
                if (j != gi) {
                    zz[r] += __expf(v0);
                    if (v0 > mx[r] || (v0 == mx[r] && j < ix[r])) { mx[r] = v0; ix[r] = j; }
                    if (v0 < mn[r] || (v0 == mn[r] && j < iN[r])) { mn[r] = v0; iN[r] = j; }
                }
                const int j1 = j + 1;
                if (j1 != gi) {
                    zz[r] += __expf(v1);
                    if (v1 > mx[r] || (v1 == mx[r] && j1 < ix[r])) { mx[r] = v1; ix[r] = j1; }
                    if (v1 < mn[r] || (v1 == mn[r] && j1 < iN[r])) { mn[r] = v1; iN[r] = j1; }
                }
            }
        }
    }

    // ---- single cross-lane reduce across the 16 tx lanes per row ----
    #pragma unroll
    for (int r = 0; r < 8; ++r) {
        float vmx = mx[r], vmn = mn[r], s = zz[r];
        int imx = ix[r], imn = iN[r];
        #pragma unroll
        for (int o = 8; o; o >>= 1) {
            float ov = __shfl_xor_sync(0xffffffffu, vmx, o);
            int   oi = __shfl_xor_sync(0xffffffffu, imx, o);
            if (ov > vmx || (ov == vmx && oi < imx)) { vmx = ov; imx = oi; }
            ov = __shfl_xor_sync(0xffffffffu, vmn, o);
            oi = __shfl_xor_sync(0xffffffffu, imn, o);
            if (ov < vmn || (ov == vmn && oi < imn)) { vmn = ov; imn = oi; }
            s += __shfl_xor_sync(0xffffffffu, s, o);
        }
        if (tx == 0) {
            const int gi = row0 + ((r < 4) ? (ty * 4 + r) : (64 + ty * 4 + (r - 4)));
            const int slot = sl * CDIM + gi;
            g_pmx[slot] = vmx; g_pix[slot] = imx;
            g_pmn[slot] = vmn; g_pin[slot] = imn;
            g_pz[slot]  = s;
        }
    }
}

// ---------------------------------------------------------------------------
// Kernel 3: combine per-slice partial state -> ms, ls, margin.
// ---------------------------------------------------------------------------
__global__ void __launch_bounds__(256) combine_kernel() {
    const int gi = blockIdx.x * 256 + threadIdx.x;
    float vmx = -2.0f, vmn = 2.0f, z = 0.0f;
    int imx = 0x7fffffff, imn = 0x7fffffff;
    #pragma unroll
    for (int s = 0; s < NSL; ++s) {
        const int slot = s * CDIM + gi;
        float a = g_pmx[slot]; int ai = g_pix[slot];
        if (a > vmx || (a == vmx && ai < imx)) { vmx = a; imx = ai; }
        float b = g_pmn[slot]; int bi = g_pin[slot];
        if (b < vmn || (b == vmn && bi < imn)) { vmn = b; imn = bi; }
        z += g_pz[slot];
    }
    g_ms[gi] = imx;
    g_ls[gi] = imn;
    g_margin[gi] = (__expf(vmx) - __expf(vmn)) / z;
}

// ---------------------------------------------------------------------------
// Kernel 4: per-row triplet term.
// ---------------------------------------------------------------------------
__global__ void __launch_bounds__(128) dist_kernel(const float* __restrict__ w) {
    const int i = blockIdx.x;
    const int t = threadIdx.x;
    const int ms = g_ms[i];
    const int ls = g_ls[i];
    float4 a = ((const float4*)(w + (size_t)i  * DDIM))[t];
    float4 b = ((const float4*)(w + (size_t)ms * DDIM))[t];
    float4 c = ((const float4*)(w + (size_t)ls * DDIM))[t];
    float dx, dm, dl;
    dx = a.x - b.x; dm  = dx * dx;
    dx = a.y - b.y; dm += dx * dx;
    dx = a.z - b.z; dm += dx * dx;
    dx = a.w - b.w; dm += dx * dx;
    dx = a.x - c.x; dl  = dx * dx;
    dx = a.y - c.y; dl += dx * dx;
    dx = a.z - c.z; dl += dx * dx;
    dx = a.w - c.w; dl += dx * dx;
    #pragma unroll
    for (int o = 16; o; o >>= 1) {
        dm += __shfl_xor_sync(0xffffffffu, dm, o);
        dl += __shfl_xor_sync(0xffffffffu, dl, o);
    }
    __shared__ float sm[4], sl_[4];
    if ((t & 31) == 0) { sm[t >> 5] = dm; sl_[t >> 5] = dl; }
    __syncthreads();
    if (t == 0) {
        float tm = sm[0] + sm[1] + sm[2] + sm[3];
        float tl = sl_[0] + sl_[1] + sl_[2] + sl_[3];
        g_terms[i] = fmaxf(0.0f, sqrtf(tm) - sqrtf(tl) + g_margin[i]);
    }
}

// ---------------------------------------------------------------------------
// Kernel 5: deterministic mean reduction.
// ---------------------------------------------------------------------------
__global__ void __launch_bounds__(256) reduce_kernel(float* __restrict__ out) {
    __shared__ float sm[256];
    const int t = threadIdx.x;
    float s = 0.0f;
    for (int i = t; i < CDIM; i += 256) s += g_terms[i];
    sm[t] = s;
    __syncthreads();
    for (int o = 128; o; o >>= 1) {
        if (t < o) sm[t] += sm[t + o];
        __syncthreads();
    }
    if (t == 0) out[0] = sm[0] * (1.0f / (float)CDIM);
}

// ---------------------------------------------------------------------------
extern "C" void kernel_launch(void* const* d_in, const int* in_sizes, int n_in,
                              void* d_out, int out_size) {
    const float* G = (const float*)d_in[0];
    const float* w = (const float*)d_in[1];
    float* out = (float*)d_out;

    normalize_kernel<<<CDIM, 128>>>(G);
    fused_sim_kernel<<<NRB * NSL, 256>>>();
    combine_kernel<<<CDIM / 256, 256>>>();
    dist_kernel<<<CDIM, 128>>>(w);
    reduce_kernel<<<1, 256>>>(out);
}